// round 1
// baseline (speedup 1.0000x reference)
#include <cuda_runtime.h>
#include <cuda_bf16.h>
#include <stdint.h>

#define NPTS 200000
#define DIM 64
#define KC 256
#define BW2 144.0f
#define TK 64
#define TN 64
#define NTILES 3125      // NPTS / TN
#define GX 111           // point-dimension blocks (444 total = 148 SM * 3)
#define ITERS 10

__device__ float g_c[2][KC][DIM];
__device__ float g_acc[KC][DIM];
__device__ float g_cnt[KC];
__device__ float g_x2[NPTS];
__device__ unsigned long long g_best[KC];
__device__ int g_seed64;

// ---------------------------------------------------------------- utilities

__global__ void x2_kernel(const float* __restrict__ x) {
    int n = blockIdx.x * blockDim.x + threadIdx.x;
    if (n >= NPTS) return;
    const float4* r = (const float4*)(x + (size_t)n * DIM);
    float s = 0.f;
#pragma unroll
    for (int i = 0; i < DIM / 4; i++) {
        float4 v = r[i];
        s = fmaf(v.x, v.x, s); s = fmaf(v.y, v.y, s);
        s = fmaf(v.z, v.z, s); s = fmaf(v.w, v.w, s);
    }
    g_x2[n] = s;
}

// Probe whether the seed buffer is int64 (reference dtype) or int32.
// Reading 128 u64 = 1024B is safe under both interpretations (256 i32 = 1KB).
__global__ void detect_kernel(const void* __restrict__ seed) {
    __shared__ int bad;
    if (threadIdx.x == 0) bad = 0;
    __syncthreads();
    const unsigned long long* s64 = (const unsigned long long*)seed;
    unsigned long long v = s64[threadIdx.x];
    if (v >= (unsigned long long)NPTS) atomicOr(&bad, 1);
    __syncthreads();
    if (threadIdx.x == 0) g_seed64 = bad ? 0 : 1;
}

__global__ void seed_kernel(const float* __restrict__ x, const void* __restrict__ seedraw) {
    int k = blockIdx.x, d = threadIdx.x;
    long long idx;
    if (g_seed64) idx = ((const long long*)seedraw)[k];
    else          idx = (long long)(((const int*)seedraw)[k]);
    g_c[0][k][d] = x[idx * DIM + d];
    g_acc[k][d] = 0.f;
    if (d == 0) { g_cnt[k] = 0.f; g_best[k] = ~0ull; }
}

__global__ void update_kernel(int it) {
    int k = blockIdx.x, d = threadIdx.x;
    float cnt = g_cnt[k];
    float v = g_acc[k][d] / cnt;
    __syncthreads();
    g_c[(it + 1) & 1][k][d] = v;
    g_acc[k][d] = 0.f;
    if (d == 0) g_cnt[k] = 0.f;
}

// ------------------------------------------- fused mask + accumulate GEMMs
// Block tile: 64 centers x 64 points, 256 threads, 4x4 register micro-tiles.
// Phase 1: S = C . X^T from Cs[d][ck] / Xt[d][p] (both float4 along
//          thread-varying index; center operand is warp-broadcast -> smem-cheap).
// Phase 2: acc[ck][d] += M[p][ck] * X[p][d] from Ms[p][ck] / Xr[p][d].

__global__ void __launch_bounds__(256) iter_kernel(const float* __restrict__ x, int it) {
    extern __shared__ float smem[];
    float* Cs  = smem;                 // [64][64]  centers, transposed
    float* c2s = Cs + 64 * 64;         // [64]
    float* Xt  = c2s + 64;             // [64][68]  x tile, transposed (padded)
    float* Xr  = Xt + 64 * 68;         // [64][68]  x tile, row-major (padded)
    float* Ms  = Xr + 64 * 68;         // [64][68]  mask tile [p][ck] (padded)
    float* x2s = Ms + 64 * 68;         // [64]

    const int tid = threadIdx.x;
    const int kb  = blockIdx.y * TK;
    const float* cin = &g_c[it & 1][0][0];

    { // centers -> Cs transposed
        int ck = tid >> 2, q = tid & 3;
        const float4* row = (const float4*)(cin + (size_t)(kb + ck) * DIM + q * 16);
#pragma unroll
        for (int i = 0; i < 4; i++) {
            float4 v = row[i];
            int dd = q * 16 + i * 4;
            Cs[(dd + 0) * TK + ck] = v.x;
            Cs[(dd + 1) * TK + ck] = v.y;
            Cs[(dd + 2) * TK + ck] = v.z;
            Cs[(dd + 3) * TK + ck] = v.w;
        }
    }
    __syncthreads();
    if (tid < TK) {
        float s = 0.f;
#pragma unroll
        for (int d = 0; d < DIM; d++) { float c = Cs[d * TK + tid]; s = fmaf(c, c, s); }
        c2s[tid] = s;
    }

    const int ty = tid >> 4, tx = tid & 15;
    const int ck0 = ty * 4, p0 = tx * 4, dq = tx * 4;

    float acc2[4][4] = {};
    float cnt4[4] = {0.f, 0.f, 0.f, 0.f};

    for (int t = blockIdx.x; t < NTILES; t += GX) {
        const int tb = t * TN;
        __syncthreads();             // prev phase2 done with Xr/Ms; covers c2s on 1st pass
        {                            // load x tile -> Xr (direct) + Xt (transposed)
            int p = tid >> 2, q = tid & 3;
            const float4* row = (const float4*)(x + (size_t)(tb + p) * DIM + q * 16);
#pragma unroll
            for (int i = 0; i < 4; i++) {
                float4 v = row[i];
                int dd = q * 16 + i * 4;
                *(float4*)(Xr + p * 68 + dd) = v;
                Xt[(dd + 0) * 68 + p] = v.x;
                Xt[(dd + 1) * 68 + p] = v.y;
                Xt[(dd + 2) * 68 + p] = v.z;
                Xt[(dd + 3) * 68 + p] = v.w;
            }
            if (tid < TN) x2s[tid] = g_x2[tb + tid];
        }
        __syncthreads();

        // phase 1: dots
        float S[4][4] = {};
#pragma unroll 4
        for (int dd = 0; dd < DIM; dd++) {
            float4 cv4 = *(const float4*)(Cs + dd * TK + ck0);
            float4 xv4 = *(const float4*)(Xt + dd * 68 + p0);
            float cv[4] = {cv4.x, cv4.y, cv4.z, cv4.w};
            float xv[4] = {xv4.x, xv4.y, xv4.z, xv4.w};
#pragma unroll
            for (int i = 0; i < 4; i++)
#pragma unroll
                for (int j = 0; j < 4; j++)
                    S[i][j] = fmaf(cv[i], xv[j], S[i][j]);
        }
        // mask -> Ms (and per-thread partial counts)
#pragma unroll
        for (int j = 0; j < 4; j++) {
            float xv2 = x2s[p0 + j];
            float4 mv;
            mv.x = (fmaf(-2.f, S[0][j], c2s[ck0 + 0] + xv2) < BW2) ? 1.f : 0.f;
            mv.y = (fmaf(-2.f, S[1][j], c2s[ck0 + 1] + xv2) < BW2) ? 1.f : 0.f;
            mv.z = (fmaf(-2.f, S[2][j], c2s[ck0 + 2] + xv2) < BW2) ? 1.f : 0.f;
            mv.w = (fmaf(-2.f, S[3][j], c2s[ck0 + 3] + xv2) < BW2) ? 1.f : 0.f;
            cnt4[0] += mv.x; cnt4[1] += mv.y; cnt4[2] += mv.z; cnt4[3] += mv.w;
            *(float4*)(Ms + (p0 + j) * 68 + ck0) = mv;
        }
        __syncthreads();

        // phase 2: acc[ck][d] += M[p][ck] * X[p][d]
#pragma unroll 4
        for (int p = 0; p < TN; p++) {
            float4 mv4 = *(const float4*)(Ms + p * 68 + ck0);
            float4 xv4 = *(const float4*)(Xr + p * 68 + dq);
            float mv[4] = {mv4.x, mv4.y, mv4.z, mv4.w};
            float xv[4] = {xv4.x, xv4.y, xv4.z, xv4.w};
#pragma unroll
            for (int i = 0; i < 4; i++)
#pragma unroll
                for (int j = 0; j < 4; j++)
                    acc2[i][j] = fmaf(mv[i], xv[j], acc2[i][j]);
        }
    }

#pragma unroll
    for (int i = 0; i < 4; i++)
#pragma unroll
        for (int j = 0; j < 4; j++)
            atomicAdd(&g_acc[kb + ck0 + i][dq + j], acc2[i][j]);

#pragma unroll
    for (int i = 0; i < 4; i++) {
        float v = cnt4[i];
#pragma unroll
        for (int off = 8; off > 0; off >>= 1)
            v += __shfl_down_sync(0xffffffffu, v, off, 16);
        if (tx == 0) atomicAdd(&g_cnt[kb + ck0 + i], v);
    }
}

// ------------------------------------------- final masked argmin pass
// mask uses centers after 9 updates (g_c[1]); distance uses centers after 10
// updates (g_c[0]). Key = (d2_bits << 32) | index  -> atomicMin reproduces
// argmin semantics (min distance, first index on ties).

__global__ void __launch_bounds__(256) final_kernel(const float* __restrict__ x) {
    extern __shared__ float smem[];
    float* C9   = smem;                // [64][64]
    float* C10  = C9 + 64 * 64;        // [64][64]
    float* c29  = C10 + 64 * 64;       // [64]
    float* c210 = c29 + 64;            // [64]
    float* Xt   = c210 + 64;           // [64][68]
    float* x2s  = Xt + 64 * 68;        // [64]

    const int tid = threadIdx.x;
    const int kb  = blockIdx.y * TK;

    {
        int ck = tid >> 2, q = tid & 3;
        const float4* r9  = (const float4*)(&g_c[1][kb + ck][0] + q * 16);
        const float4* r10 = (const float4*)(&g_c[0][kb + ck][0] + q * 16);
#pragma unroll
        for (int i = 0; i < 4; i++) {
            float4 a = r9[i], b = r10[i];
            int dd = q * 16 + i * 4;
            C9[(dd + 0) * TK + ck] = a.x; C9[(dd + 1) * TK + ck] = a.y;
            C9[(dd + 2) * TK + ck] = a.z; C9[(dd + 3) * TK + ck] = a.w;
            C10[(dd + 0) * TK + ck] = b.x; C10[(dd + 1) * TK + ck] = b.y;
            C10[(dd + 2) * TK + ck] = b.z; C10[(dd + 3) * TK + ck] = b.w;
        }
    }
    __syncthreads();
    if (tid < TK) {
        float s9 = 0.f, s10 = 0.f;
#pragma unroll
        for (int d = 0; d < DIM; d++) {
            float a = C9[d * TK + tid];  s9  = fmaf(a, a, s9);
            float b = C10[d * TK + tid]; s10 = fmaf(b, b, s10);
        }
        c29[tid] = s9; c210[tid] = s10;
    }

    const int ty = tid >> 4, tx = tid & 15;
    const int ck0 = ty * 4, p0 = tx * 4;
    unsigned long long best[4] = {~0ull, ~0ull, ~0ull, ~0ull};

    for (int t = blockIdx.x; t < NTILES; t += GX) {
        const int tb = t * TN;
        __syncthreads();
        {
            int p = tid >> 2, q = tid & 3;
            const float4* row = (const float4*)(x + (size_t)(tb + p) * DIM + q * 16);
#pragma unroll
            for (int i = 0; i < 4; i++) {
                float4 v = row[i];
                int dd = q * 16 + i * 4;
                Xt[(dd + 0) * 68 + p] = v.x;
                Xt[(dd + 1) * 68 + p] = v.y;
                Xt[(dd + 2) * 68 + p] = v.z;
                Xt[(dd + 3) * 68 + p] = v.w;
            }
            if (tid < TN) x2s[tid] = g_x2[tb + tid];
        }
        __syncthreads();

        float S9[4][4] = {}, S10[4][4] = {};
#pragma unroll 2
        for (int dd = 0; dd < DIM; dd++) {
            float4 c9v = *(const float4*)(C9 + dd * TK + ck0);
            float4 cav = *(const float4*)(C10 + dd * TK + ck0);
            float4 xv4 = *(const float4*)(Xt + dd * 68 + p0);
            float a9[4] = {c9v.x, c9v.y, c9v.z, c9v.w};
            float aa[4] = {cav.x, cav.y, cav.z, cav.w};
            float xv[4] = {xv4.x, xv4.y, xv4.z, xv4.w};
#pragma unroll
            for (int i = 0; i < 4; i++)
#pragma unroll
                for (int j = 0; j < 4; j++) {
                    S9[i][j]  = fmaf(a9[i], xv[j], S9[i][j]);
                    S10[i][j] = fmaf(aa[i], xv[j], S10[i][j]);
                }
        }
#pragma unroll
        for (int j = 0; j < 4; j++) {
            float xv2 = x2s[p0 + j];
            unsigned idx = (unsigned)(tb + p0 + j);
#pragma unroll
            for (int i = 0; i < 4; i++) {
                float d2m = fmaf(-2.f, S9[i][j], c29[ck0 + i] + xv2);
                if (d2m < BW2) {
                    float d2 = fmaf(-2.f, S10[i][j], c210[ck0 + i] + xv2);
                    d2 = fmaxf(d2, 0.f);
                    unsigned long long key =
                        ((unsigned long long)__float_as_uint(d2) << 32) | idx;
                    if (key < best[i]) best[i] = key;
                }
            }
        }
    }

#pragma unroll
    for (int i = 0; i < 4; i++) {
        unsigned long long v = best[i];
#pragma unroll
        for (int off = 8; off > 0; off >>= 1) {
            unsigned long long o = __shfl_down_sync(0xffffffffu, v, off, 16);
            if (o < v) v = o;
        }
        if (tx == 0) atomicMin(&g_best[kb + ck0 + i], v);
    }
}

// ---------------------------------------------------------------- epilogue

__global__ void zero_out(float* out, int n) {
    int i = blockIdx.x * blockDim.x + threadIdx.x;
    if (i < n) out[i] = 0.f;
}

__global__ void finish_kernel(float* __restrict__ out, const float* __restrict__ x,
                              int out_size) {
    int k = blockIdx.x, d = threadIdx.x;
    if (out_size >= KC * DIM)
        out[k * DIM + d] = g_c[0][k][d];
    unsigned long long b = g_best[k];
    unsigned idx = (b == ~0ull) ? 0u : (unsigned)(b & 0xffffffffu);
    if (out_size >= 2 * KC * DIM)
        out[KC * DIM + k * DIM + d] = x[(size_t)idx * DIM + d];
    if (d == 0 && out_size >= 2 * KC * DIM + KC)
        out[2 * KC * DIM + k] = (float)idx;
}

// ---------------------------------------------------------------- launcher

extern "C" void kernel_launch(void* const* d_in, const int* in_sizes, int n_in,
                              void* d_out, int out_size) {
    const float* x = (const float*)d_in[0];
    const void* seed = d_in[1];
    float* out = (float*)d_out;
    (void)in_sizes; (void)n_in;

    const size_t iterSmem  = (size_t)(64 * 64 + 64 + 3 * 64 * 68 + 64) * sizeof(float);
    const size_t finalSmem = (size_t)(2 * 64 * 64 + 2 * 64 + 64 * 68 + 64) * sizeof(float);
    cudaFuncSetAttribute(iter_kernel,  cudaFuncAttributeMaxDynamicSharedMemorySize, (int)iterSmem);
    cudaFuncSetAttribute(final_kernel, cudaFuncAttributeMaxDynamicSharedMemorySize, (int)finalSmem);

    x2_kernel<<<(NPTS + 255) / 256, 256>>>(x);
    detect_kernel<<<1, 128>>>(seed);
    seed_kernel<<<KC, DIM>>>(x, seed);

    for (int it = 0; it < ITERS; it++) {
        iter_kernel<<<dim3(GX, KC / TK), 256, iterSmem>>>(x, it);
        update_kernel<<<KC, DIM>>>(it);
    }

    final_kernel<<<dim3(GX, KC / TK), 256, finalSmem>>>(x);

    if (out_size > 0)
        zero_out<<<(out_size + 255) / 256, 256>>>(out, out_size);
    finish_kernel<<<KC, DIM>>>(out, x, out_size);
}